// round 9
// baseline (speedup 1.0000x reference)
#include <cuda_runtime.h>
#include <cuda_bf16.h>

// MeanAggregator: out[r,:] = mean over UNIQUE neighbors c of row r of embed[c,:]
// row_idx sorted ascending. D = 300 floats = 75 float4.
// Design: one warp per (row, slot); slot s covers float4 indices s*32+lane.
// GATHER-ALL + SUBTRACT-DUPLICATES (dup detect deferred past gather).
// NEW (R9): bulk prefetch.global.L2 of every neighbor row-chunk immediately
// after the col indices arrive -> whole-row MLP, gather LDGs become L2 hits.

#define AGG_D4   75
#define AGG_MAXL 96            // fast-path cap: 3 chunks (L ~ Poisson(32), max ~70)
#define AGG_MAXB 65536
#define WARPS_PB 8             // 256-thread blocks
#define ROW_BYTES (AGG_D4 * 16)   // 1200

__device__ int g_row_start[AGG_MAXB + 1];

// CSR row pointers by diff-scatter over the sorted row_idx (O(E), contiguous loads).
__global__ void build_row_starts(const int* __restrict__ row_idx, int E, int B) {
    int i = blockIdx.x * blockDim.x + threadIdx.x;
    if (i > E) return;
    if (i == 0) {
        int cur = row_idx[0];
        for (int v = 0; v <= cur; ++v) g_row_start[v] = 0;
    } else if (i == E) {
        int prev = row_idx[E - 1];
        for (int v = prev + 1; v <= B; ++v) g_row_start[v] = E;
    } else {
        int prev = row_idx[i - 1];
        int cur  = row_idx[i];
        for (int v = prev + 1; v <= cur; ++v) g_row_start[v] = i;
    }
}

__global__ __launch_bounds__(WARPS_PB * 32) void mean_agg_kernel(
    const int*    __restrict__ col_idx,
    const float4* __restrict__ embed4,   // [U, 75]
    float4*       __restrict__ out4,     // [B, 75]
    int B)
{
    const int w    = threadIdx.x >> 5;
    const int lane = threadIdx.x & 31;
    const int gw   = blockIdx.x * WARPS_PB + w;   // global warp id
    const int r    = gw / 3;                      // row
    const int slot = gw - r * 3;                  // LDG slot 0/1/2
    if (r >= B) return;                           // warp-uniform

    const int  d4  = slot * 32 + lane;            // my float4 index in [0,75)
    const bool act = (d4 < AGG_D4);               // slot 2: lanes 0..10 only

    const int start = g_row_start[r];
    const int L     = g_row_start[r + 1] - start;

    __shared__ int s_col[WARPS_PB][AGG_MAXL];
    int* sc = s_col[w];

    float4 acc = make_float4(0.f, 0.f, 0.f, 0.f);
    const unsigned lt = (1u << lane) - 1u;
    const float4* __restrict__ e = embed4 + d4;
    int Lu = 0;

    if (L <= AGG_MAXL) {
        // ---- 3 independent coalesced chunk loads of col indices ----
        const int j1 = 32 + lane, j2 = 64 + lane;
        int c0 = (lane < L) ? col_idx[start + lane] : -(lane + 1);
        int c1 = (j1   < L) ? col_idx[start + j1]   : -(lane + 1);
        int c2 = (j2   < L) ? col_idx[start + j2]   : -(lane + 1);
        sc[lane] = c0;
        if (j1 < L) sc[j1] = c1;
        if (j2 < L) sc[j2] = c2;
        __syncwarp();

        // ---- bulk L2 prefetch: all neighbors, whole warp-slot chunk ----
        // Lane layout: 8 neighbors x 4 lines per instruction. Fire-and-forget;
        // no registers, no scoreboard -> MLP ~= L while we set up the gather.
        {
            const int nb = lane >> 2;             // neighbor within group (0..7)
            const int lp = lane & 3;              // 128B line within 512B chunk
            const int boff = slot * 512 + lp * 128;
            if (boff < ROW_BYTES) {               // clamp (slot 2 chunk is 176B)
                const char* base = (const char*)embed4 + boff;
                for (int b = 0; b < L; b += 8) {
                    int j = b + nb;
                    if (j < L) {
                        const char* p = base + (size_t)sc[j] * ROW_BYTES;
                        asm volatile("prefetch.global.L2 [%0];" :: "l"(p));
                    }
                }
            }
        }

        // ---- main gather over ALL L entries (dups included): unroll-8 ----
        if (act) {
            int j = 0;
            for (; j + 8 <= L; j += 8) {
                float4 v0 = e[(size_t)sc[j]     * AGG_D4];
                float4 v1 = e[(size_t)sc[j + 1] * AGG_D4];
                float4 v2 = e[(size_t)sc[j + 2] * AGG_D4];
                float4 v3 = e[(size_t)sc[j + 3] * AGG_D4];
                float4 v4 = e[(size_t)sc[j + 4] * AGG_D4];
                float4 v5 = e[(size_t)sc[j + 5] * AGG_D4];
                float4 v6 = e[(size_t)sc[j + 6] * AGG_D4];
                float4 v7 = e[(size_t)sc[j + 7] * AGG_D4];
                acc.x += (v0.x + v1.x + v2.x + v3.x) + (v4.x + v5.x + v6.x + v7.x);
                acc.y += (v0.y + v1.y + v2.y + v3.y) + (v4.y + v5.y + v6.y + v7.y);
                acc.z += (v0.z + v1.z + v2.z + v3.z) + (v4.z + v5.z + v6.z + v7.z);
                acc.w += (v0.w + v1.w + v2.w + v3.w) + (v4.w + v5.w + v6.w + v7.w);
            }
            for (; j + 4 <= L; j += 4) {
                float4 v0 = e[(size_t)sc[j]     * AGG_D4];
                float4 v1 = e[(size_t)sc[j + 1] * AGG_D4];
                float4 v2 = e[(size_t)sc[j + 2] * AGG_D4];
                float4 v3 = e[(size_t)sc[j + 3] * AGG_D4];
                acc.x += v0.x + v1.x + v2.x + v3.x;
                acc.y += v0.y + v1.y + v2.y + v3.y;
                acc.z += v0.z + v1.z + v2.z + v3.z;
                acc.w += v0.w + v1.w + v2.w + v3.w;
            }
            for (; j < L; ++j) {
                float4 v = e[(size_t)sc[j] * AGG_D4];
                acc.x += v.x; acc.y += v.y; acc.z += v.z; acc.w += v.w;
            }
        }

        // ---- duplicate detection AFTER the gather (all lanes participate) ----
        unsigned p0m = __match_any_sync(0xffffffffu, c0);
        bool d0 = (lane < L) && ((p0m & lt) != 0);
        bool d1 = false, d2 = false;
        if (L > 32) {
            unsigned p1m = __match_any_sync(0xffffffffu, c1);
            d1 = (j1 < L) && ((p1m & lt) != 0);
            if (!d1 && j1 < L) {
                for (int i = 0; i < 32; ++i)
                    if (sc[i] == c1) { d1 = true; break; }
            }
            if (L > 64) {
                unsigned p2m = __match_any_sync(0xffffffffu, c2);
                d2 = (j2 < L) && ((p2m & lt) != 0);
                if (!d2 && j2 < L) {
                    for (int i = 0; i < 64; ++i)
                        if (sc[i] == c2) { d2 = true; break; }
                }
            }
        }
        const unsigned m0 = __ballot_sync(0xffffffffu, d0);
        const unsigned m1 = __ballot_sync(0xffffffffu, d1);
        const unsigned m2 = __ballot_sync(0xffffffffu, d2);
        Lu = L - (__popc(m0) + __popc(m1) + __popc(m2));

        // ---- subtract duplicate occurrences (almost always all-zero masks) ----
        if (act && (m0 | m1 | m2)) {
            unsigned masks[3] = { m0, m1, m2 };
            #pragma unroll
            for (int k = 0; k < 3; ++k) {
                unsigned m = masks[k];
                while (m) {
                    int b = __ffs(m) - 1; m &= m - 1;
                    float4 v = e[(size_t)sc[k * 32 + b] * AGG_D4];
                    acc.x -= v.x; acc.y -= v.y; acc.z -= v.z; acc.w -= v.w;
                }
            }
        }
    } else {
        // Unreachable-for-this-data fallback: O(L^2) global dedup, direct accumulate.
        for (int j = 0; j < L; ++j) {
            int c = col_idx[start + j];
            bool valid = true;
            for (int i = 0; i < j; ++i)
                if (col_idx[start + i] == c) { valid = false; break; }
            if (!valid) continue;
            ++Lu;
            if (act) {
                float4 v = e[(size_t)c * AGG_D4];
                acc.x += v.x; acc.y += v.y; acc.z += v.z; acc.w += v.w;
            }
        }
    }

    if (act) {
        const float inv = 1.0f / fmaxf((float)Lu, 1e-8f);
        float4 t;
        t.x = acc.x * inv; t.y = acc.y * inv; t.z = acc.z * inv; t.w = acc.w * inv;
        out4[(size_t)r * AGG_D4 + d4] = t;
    }
}

extern "C" void kernel_launch(void* const* d_in, const int* in_sizes, int n_in,
                              void* d_out, int out_size) {
    const int*   row_idx = (const int*)  d_in[0];
    const int*   col_idx = (const int*)  d_in[1];
    const float* embed   = (const float*)d_in[2];
    float*       out     = (float*)      d_out;

    const int E = in_sizes[0];
    const int B = out_size / 300;

    const int total_warps = 3 * B;
    build_row_starts<<<(E + 1 + 255) / 256, 256>>>(row_idx, E, B);
    mean_agg_kernel<<<(total_warps + WARPS_PB - 1) / WARPS_PB, WARPS_PB * 32>>>(
        col_idx, (const float4*)embed, (float4*)out, B);
}